// round 3
// baseline (speedup 1.0000x reference)
#include <cuda_runtime.h>

#define NROWS   16384
#define INC     512
#define NG      64
#define NF      24
#define NO      16
#define ACCC    3584
#define RT      16
#define SMEM_BYTES (ACCC * RT * 4)   // 229376

static __device__ __forceinline__ unsigned long long pk2(float a, float b) {
    unsigned long long r;
    asm("mov.b64 %0, {%1, %2};" : "=l"(r) : "f"(a), "f"(b));
    return r;
}
static __device__ __forceinline__ void up2(unsigned long long v, float &a, float &b) {
    asm("mov.b64 {%0, %1}, %2;" : "=f"(a), "=f"(b) : "l"(v));
}
static __device__ __forceinline__ unsigned long long fma2(unsigned long long a,
                                                          unsigned long long b,
                                                          unsigned long long c) {
    unsigned long long d;
    asm("fma.rn.f32x2 %0, %1, %2, %3;" : "=l"(d) : "l"(a), "l"(b), "l"(c));
    return d;
}
// tanh(x) = 1 - 2/(exp(2x)+1); ex2.approx+rcp.approx -> ~1e-6 rel err, saturates correctly
static __device__ __forceinline__ float tanhfast(float x) {
    float t;
    asm("ex2.approx.f32 %0, %1;" : "=f"(t) : "f"(x * 2.8853900817779268f));
    float r;
    asm("rcp.approx.f32 %0, %1;" : "=f"(r) : "f"(t + 1.0f));
    return fmaf(-2.0f, r, 1.0f);
}

// One grouped layer for this thread's (g, q): gather F cols, 24x16 GEMM into
// f32x2 o-pair accumulators over 4 rows, tanh, store back swizzled.
static __device__ __forceinline__ void glayer(float* sh, int g, int q,
                                              const float* __restrict__ W,
                                              const float* __restrict__ bia,
                                              const int* __restrict__ idx,
                                              int colbase)
{
    unsigned long long acc[4][8];
    {
        const float2* b2 = reinterpret_cast<const float2*>(bia + g * NO);
        #pragma unroll
        for (int op = 0; op < 8; op++) {
            float2 bb = __ldg(&b2[op]);
            unsigned long long bv = pk2(bb.x, bb.y);
            #pragma unroll
            for (int r = 0; r < 4; r++) acc[r][op] = bv;
        }
    }
    const int* gi = idx + g * NF;
    const ulonglong2* W2 = reinterpret_cast<const ulonglong2*>(W + g * NF * NO);

    #pragma unroll
    for (int f = 0; f < NF; f++) {
        int c = __ldg(&gi[f]);
        int slot = q ^ (c & 3);
        float4 a4 = *reinterpret_cast<const float4*>(sh + c * 16 + slot * 4);
        unsigned long long a0 = pk2(a4.x, a4.x);
        unsigned long long a1 = pk2(a4.y, a4.y);
        unsigned long long a2 = pk2(a4.z, a4.z);
        unsigned long long a3 = pk2(a4.w, a4.w);
        ulonglong2 u0 = __ldg(&W2[f * 4 + 0]);
        ulonglong2 u1 = __ldg(&W2[f * 4 + 1]);
        ulonglong2 u2 = __ldg(&W2[f * 4 + 2]);
        ulonglong2 u3 = __ldg(&W2[f * 4 + 3]);
        unsigned long long wp[8] = {u0.x, u0.y, u1.x, u1.y, u2.x, u2.y, u3.x, u3.y};
        #pragma unroll
        for (int op = 0; op < 8; op++) {
            acc[0][op] = fma2(a0, wp[op], acc[0][op]);
            acc[1][op] = fma2(a1, wp[op], acc[1][op]);
            acc[2][op] = fma2(a2, wp[op], acc[2][op]);
            acc[3][op] = fma2(a3, wp[op], acc[3][op]);
        }
    }

    float hv[4][NO];
    #pragma unroll
    for (int r = 0; r < 4; r++) {
        #pragma unroll
        for (int op = 0; op < 8; op++)
            up2(acc[r][op], hv[r][2 * op], hv[r][2 * op + 1]);
    }
    #pragma unroll
    for (int r = 0; r < 4; r++) {
        #pragma unroll
        for (int o = 0; o < NO; o++)
            hv[r][o] = tanhfast(hv[r][o]);
    }
    #pragma unroll
    for (int o = 0; o < NO; o++) {
        int c = colbase + g * NO + o;
        int slot = q ^ (c & 3);
        *reinterpret_cast<float4*>(sh + c * 16 + slot * 4) =
            make_float4(hv[0][o], hv[1][o], hv[2][o], hv[3][o]);
    }
}

__global__ void __launch_bounds__(256, 1)
model_kernel(const float* __restrict__ x,
             const float* __restrict__ W1, const float* __restrict__ b1,
             const float* __restrict__ W2, const float* __restrict__ b2,
             const float* __restrict__ W3, const float* __restrict__ b3,
             const float* __restrict__ Wo, const float* __restrict__ bo,
             const int* __restrict__ idx1, const int* __restrict__ idx2,
             const int* __restrict__ idx3, const int* __restrict__ idxo,
             float* __restrict__ out)
{
    extern __shared__ float sh[];  // [ACCC][16] with quad-XOR swizzle
    const int t = threadIdx.x;
    const int rowbase = blockIdx.x * RT;

    // ---- Stage x tile (16 rows x 512 cols) into swizzled SMEM ----
    {
        const float* xb = x + (size_t)rowbase * INC;
        #pragma unroll
        for (int it = 0; it < 8; it++) {
            int item = t + it * 256;        // 0..2047 -> (quad, col)
            int q = item >> 9;
            int c = item & 511;
            float v0 = __ldg(&xb[(q * 4 + 0) * INC + c]);
            float v1 = __ldg(&xb[(q * 4 + 1) * INC + c]);
            float v2 = __ldg(&xb[(q * 4 + 2) * INC + c]);
            float v3 = __ldg(&xb[(q * 4 + 3) * INC + c]);
            int slot = q ^ (c & 3);
            *reinterpret_cast<float4*>(sh + c * 16 + slot * 4) =
                make_float4(v0, v1, v2, v3);
        }
    }
    __syncthreads();

    const int g = t >> 2;   // group 0..63
    const int q = t & 3;    // row quad 0..3

    glayer(sh, g, q, W1, b1, idx1, 512);
    __syncthreads();
    glayer(sh, g, q, W2, b2, idx2, 1536);
    __syncthreads();
    glayer(sh, g, q, W3, b3, idx3, 2560);
    __syncthreads();

    // ---- Output layer: 4 groups x 48 f x 16 o, linear ----
    {
        int ot = t & 15;
        int og = (t >> 4) & 3;
        int oq = t >> 6;
        float bias = __ldg(&bo[og * 16 + ot]);
        float h0 = bias, h1 = bias, h2 = bias, h3 = bias;
        const int* gi = idxo + og * 48;
        const float* w = Wo + og * 48 * 16 + ot;
        #pragma unroll
        for (int f = 0; f < 48; f++) {
            int c = __ldg(&gi[f]);
            int slot = oq ^ (c & 3);
            float4 a4 = *reinterpret_cast<const float4*>(sh + c * 16 + slot * 4);
            float wf = __ldg(&w[f * 16]);
            h0 = fmaf(a4.x, wf, h0);
            h1 = fmaf(a4.y, wf, h1);
            h2 = fmaf(a4.z, wf, h2);
            h3 = fmaf(a4.w, wf, h3);
        }
        float* ob = out + (size_t)(rowbase + oq * 4) * 64 + og * 16 + ot;
        ob[0]       = h0;
        ob[64]      = h1;
        ob[128]     = h2;
        ob[192]     = h3;
    }
}

extern "C" void kernel_launch(void* const* d_in, const int* in_sizes, int n_in,
                              void* d_out, int out_size)
{
    const float* x   = (const float*)d_in[0];
    const float* W1  = (const float*)d_in[1];
    const float* b1  = (const float*)d_in[2];
    const float* W2  = (const float*)d_in[3];
    const float* b2  = (const float*)d_in[4];
    const float* W3  = (const float*)d_in[5];
    const float* b3  = (const float*)d_in[6];
    const float* Wo  = (const float*)d_in[7];
    const float* bo  = (const float*)d_in[8];
    const int*   i1  = (const int*)d_in[9];
    const int*   i2  = (const int*)d_in[10];
    const int*   i3  = (const int*)d_in[11];
    const int*   io  = (const int*)d_in[12];
    float*       out = (float*)d_out;

    cudaFuncSetAttribute(model_kernel,
                         cudaFuncAttributeMaxDynamicSharedMemorySize, SMEM_BYTES);
    model_kernel<<<NROWS / RT, 256, SMEM_BYTES>>>(
        x, W1, b1, W2, b2, W3, b3, Wo, bo, i1, i2, i3, io, out);
}

// round 4
// speedup vs baseline: 1.0665x; 1.0665x over previous
#include <cuda_runtime.h>

#define NROWS   16384
#define INC     512
#define NG      64
#define NF      24
#define NO      16
#define ACCC    3584
#define RT      16
#define NTHR    512
#define SMEM_BYTES (ACCC * RT * 4)   // 229376

static __device__ __forceinline__ unsigned long long pk2(float a, float b) {
    unsigned long long r;
    asm("mov.b64 %0, {%1, %2};" : "=l"(r) : "f"(a), "f"(b));
    return r;
}
static __device__ __forceinline__ void up2(unsigned long long v, float &a, float &b) {
    asm("mov.b64 {%0, %1}, %2;" : "=f"(a), "=f"(b) : "l"(v));
}
static __device__ __forceinline__ unsigned long long fma2(unsigned long long a,
                                                          unsigned long long b,
                                                          unsigned long long c) {
    unsigned long long d;
    asm("fma.rn.f32x2 %0, %1, %2, %3;" : "=l"(d) : "l"(a), "l"(b), "l"(c));
    return d;
}
// tanh(x) = 1 - 2/(exp(2x)+1); ex2.approx+rcp.approx -> ~1e-6 rel err, saturates correctly
static __device__ __forceinline__ float tanhfast(float x) {
    float t;
    asm("ex2.approx.f32 %0, %1;" : "=f"(t) : "f"(x * 2.8853900817779268f));
    float r;
    asm("rcp.approx.f32 %0, %1;" : "=f"(r) : "f"(t + 1.0f));
    return fmaf(-2.0f, r, 1.0f);
}

// SMEM layout: [col][16 rows], rows stored as 8 pairs of float2;
// pair p of column c lives at slot (p ^ (c & 7)).
// One grouped layer for thread's (g, p): gather F cols (2 rows), 24x16 GEMM
// into f32x2 o-pair accumulators, tanh, store back swizzled.
static __device__ __forceinline__ void glayer(float* sh, int g, int p,
                                              const float* __restrict__ W,
                                              const float* __restrict__ bia,
                                              const int* __restrict__ idx,
                                              int colbase)
{
    unsigned long long acc[2][8];
    {
        const float2* b2 = reinterpret_cast<const float2*>(bia + g * NO);
        #pragma unroll
        for (int op = 0; op < 8; op++) {
            float2 bb = __ldg(&b2[op]);
            unsigned long long bv = pk2(bb.x, bb.y);
            acc[0][op] = bv;
            acc[1][op] = bv;
        }
    }
    const int* gi = idx + g * NF;
    const ulonglong2* W2 = reinterpret_cast<const ulonglong2*>(W + g * NF * NO);

    #pragma unroll
    for (int f = 0; f < NF; f++) {
        int c = __ldg(&gi[f]);
        int slot = p ^ (c & 7);
        float2 a2 = *reinterpret_cast<const float2*>(sh + c * 16 + slot * 2);
        unsigned long long a0 = pk2(a2.x, a2.x);
        unsigned long long a1 = pk2(a2.y, a2.y);
        ulonglong2 u0 = __ldg(&W2[f * 4 + 0]);
        ulonglong2 u1 = __ldg(&W2[f * 4 + 1]);
        ulonglong2 u2 = __ldg(&W2[f * 4 + 2]);
        ulonglong2 u3 = __ldg(&W2[f * 4 + 3]);
        unsigned long long wp[8] = {u0.x, u0.y, u1.x, u1.y, u2.x, u2.y, u3.x, u3.y};
        #pragma unroll
        for (int op = 0; op < 8; op++) {
            acc[0][op] = fma2(a0, wp[op], acc[0][op]);
            acc[1][op] = fma2(a1, wp[op], acc[1][op]);
        }
    }

    float hv[2][NO];
    #pragma unroll
    for (int r = 0; r < 2; r++) {
        #pragma unroll
        for (int op = 0; op < 8; op++)
            up2(acc[r][op], hv[r][2 * op], hv[r][2 * op + 1]);
    }
    #pragma unroll
    for (int r = 0; r < 2; r++) {
        #pragma unroll
        for (int o = 0; o < NO; o++)
            hv[r][o] = tanhfast(hv[r][o]);
    }
    #pragma unroll
    for (int o = 0; o < NO; o++) {
        int c = colbase + g * NO + o;
        int slot = p ^ (c & 7);
        *reinterpret_cast<float2*>(sh + c * 16 + slot * 2) =
            make_float2(hv[0][o], hv[1][o]);
    }
}

__global__ void __launch_bounds__(NTHR, 1)
model_kernel(const float* __restrict__ x,
             const float* __restrict__ W1, const float* __restrict__ b1,
             const float* __restrict__ W2, const float* __restrict__ b2,
             const float* __restrict__ W3, const float* __restrict__ b3,
             const float* __restrict__ Wo, const float* __restrict__ bo,
             const int* __restrict__ idx1, const int* __restrict__ idx2,
             const int* __restrict__ idx3, const int* __restrict__ idxo,
             float* __restrict__ out)
{
    extern __shared__ float sh[];  // [ACCC][16], 8B-slot pair swizzle
    const int t = threadIdx.x;
    const int rowbase = blockIdx.x * RT;

    // ---- Stage x tile (16 rows x 512 cols) into swizzled SMEM ----
    {
        const float* xb = x + (size_t)rowbase * INC;
        #pragma unroll
        for (int it = 0; it < 8; it++) {
            int item = t + it * NTHR;       // 0..4095 -> (pair, col)
            int p = item >> 9;              // 0..7
            int c = item & 511;
            float v0 = __ldg(&xb[(p * 2 + 0) * INC + c]);
            float v1 = __ldg(&xb[(p * 2 + 1) * INC + c]);
            int slot = p ^ (c & 7);
            *reinterpret_cast<float2*>(sh + c * 16 + slot * 2) =
                make_float2(v0, v1);
        }
    }
    __syncthreads();

    const int g = t >> 3;   // group 0..63
    const int p = t & 7;    // row pair 0..7

    glayer(sh, g, p, W1, b1, idx1, 512);
    __syncthreads();
    glayer(sh, g, p, W2, b2, idx2, 1536);
    __syncthreads();
    glayer(sh, g, p, W3, b3, idx3, 2560);
    __syncthreads();

    // ---- Output layer: 4 groups x 48 f x 16 o, linear ----
    {
        int ot = t & 15;
        int og = (t >> 4) & 3;
        int oq = t >> 6;                    // row pair 0..7
        float bias = __ldg(&bo[og * 16 + ot]);
        float h0 = bias, h1 = bias;
        const int* gi = idxo + og * 48;
        const float* w = Wo + og * 48 * 16 + ot;
        #pragma unroll
        for (int f = 0; f < 48; f++) {
            int c = __ldg(&gi[f]);
            int slot = oq ^ (c & 7);
            float2 a2 = *reinterpret_cast<const float2*>(sh + c * 16 + slot * 2);
            float wf = __ldg(&w[f * 16]);
            h0 = fmaf(a2.x, wf, h0);
            h1 = fmaf(a2.y, wf, h1);
        }
        float* ob = out + (size_t)(rowbase + oq * 2) * 64 + og * 16 + ot;
        ob[0]  = h0;
        ob[64] = h1;
    }
}

extern "C" void kernel_launch(void* const* d_in, const int* in_sizes, int n_in,
                              void* d_out, int out_size)
{
    const float* x   = (const float*)d_in[0];
    const float* W1  = (const float*)d_in[1];
    const float* b1  = (const float*)d_in[2];
    const float* W2  = (const float*)d_in[3];
    const float* b2  = (const float*)d_in[4];
    const float* W3  = (const float*)d_in[5];
    const float* b3  = (const float*)d_in[6];
    const float* Wo  = (const float*)d_in[7];
    const float* bo  = (const float*)d_in[8];
    const int*   i1  = (const int*)d_in[9];
    const int*   i2  = (const int*)d_in[10];
    const int*   i3  = (const int*)d_in[11];
    const int*   io  = (const int*)d_in[12];
    float*       out = (float*)d_out;

    cudaFuncSetAttribute(model_kernel,
                         cudaFuncAttributeMaxDynamicSharedMemorySize, SMEM_BYTES);
    model_kernel<<<NROWS / RT, NTHR, SMEM_BYTES>>>(
        x, W1, b1, W2, b2, W3, b3, Wo, bo, i1, i2, i3, io, out);
}